// round 9
// baseline (speedup 1.0000x reference)
#include <cuda_runtime.h>

#define BB 4
#define TT 16
#define HH 64
#define WW 64
#define CC 32
#define FF 64
#define OC 256   // 4*F
#define PS 613   // smem plane stride (odd mod 32 -> conflict-free chunk loads)
#define HALO 612 // 18*34 halo plane elements

// ---------------- scratch (device globals; no allocations allowed) ----------
__device__ float g_xn[(size_t)BB*TT*HH*WW*CC];
__device__ float g_zx[(size_t)BB*TT*HH*WW*OC];
__device__ float g_ha[(size_t)BB*HH*WW*FF];   // h ping
__device__ float g_hb[(size_t)BB*HH*WW*FF];   // h pong
__device__ float g_c [(size_t)BB*HH*WW*FF];

typedef unsigned long long u64;

// ---------------- f32x2 packed helpers (Blackwell) ---------------------------
__device__ __forceinline__ void fma2(u64& d, u64 a, u64 b) {
    asm("fma.rn.f32x2 %0, %1, %2, %0;" : "+l"(d) : "l"(a), "l"(b));
}
__device__ __forceinline__ u64 bcast2(float x) {
    u64 r; asm("mov.b64 %0, {%1, %1};" : "=l"(r) : "f"(x)); return r;
}
__device__ __forceinline__ u64 pack2f(float x, float y) {
    u64 r; asm("mov.b64 %0, {%1, %2};" : "=l"(r) : "f"(x), "f"(y)); return r;
}
__device__ __forceinline__ float2 unpack2(u64 v) {
    float2 f; asm("mov.b64 {%0, %1}, %2;" : "=f"(f.x), "=f"(f.y) : "l"(v)); return f;
}

// ---------------- LayerNorm over channel axis (C=32 = one warp) -------------
__global__ void ln_kernel(const float* __restrict__ x,
                          const float* __restrict__ gamma,
                          const float* __restrict__ beta) {
    int row  = blockIdx.x * 8 + (threadIdx.x >> 5);
    int lane = threadIdx.x & 31;
    float v = x[(size_t)row * CC + lane];
    float s = v, s2 = v * v;
    #pragma unroll
    for (int o = 16; o; o >>= 1) {
        s  += __shfl_xor_sync(0xffffffffu, s,  o);
        s2 += __shfl_xor_sync(0xffffffffu, s2, o);
    }
    float mu  = s * (1.f / 32.f);
    float var = s2 * (1.f / 32.f) - mu * mu;
    float inv = rsqrtf(var + 1e-3f);
    g_xn[(size_t)row * CC + lane] = (v - mu) * inv * gamma[lane] + beta[lane];
}

// ---------------- zero h(ping), c --------------------------------------------
__global__ void zero_hc_kernel() {
    int i = blockIdx.x * blockDim.x + threadIdx.x;
    if (i < BB * HH * WW * FF) { g_ha[i] = 0.f; g_c[i] = 0.f; }
}

// ---------------- input conv: zx = conv3x3(xn, Wx) + b ----------------------
// grid: (ocb=8, tile=8, bt=64), block 256, tile 32x16, 2 px/thread, f32x2 FMA.
__global__ __launch_bounds__(256, 2) void convx_kernel(const float* __restrict__ Wx,
                                                       const float* __restrict__ bias) {
    extern __shared__ float sm[];
    float* s_in = sm;                 // 32 * 613
    float* s_w  = sm + 32 * PS;       // 9216

    int ocb  = blockIdx.x;
    int tile = blockIdx.y;
    int bt   = blockIdx.z;
    int tid  = threadIdx.x;
    int ty0 = (tile >> 1) * 16, tx0 = (tile & 1) * 32;
    int oc0 = ocb * 32;
    int px = tid & 31, py = tid >> 5;
    int y1 = ty0 + py, y2 = y1 + 8, x = tx0 + px;

    const float* xin = g_xn + (size_t)bt * HH * WW * CC;

    for (int i = tid; i < 8 * HALO; i += 256) {
        int c4 = (i & 7) * 4, sp = i >> 3;
        int ry = sp / 34, rx = sp - ry * 34;
        int gy = ty0 - 1 + ry, gx = tx0 - 1 + rx;
        float4 v = make_float4(0.f, 0.f, 0.f, 0.f);
        if (gy >= 0 && gy < HH && gx >= 0 && gx < WW)
            v = *(const float4*)(xin + ((size_t)gy * WW + gx) * CC + c4);
        s_in[(c4+0)*PS + sp] = v.x; s_in[(c4+1)*PS + sp] = v.y;
        s_in[(c4+2)*PS + sp] = v.z; s_in[(c4+3)*PS + sp] = v.w;
    }
    for (int i = tid; i < 9 * CC * 32; i += 256) {
        int oc = i & 31, rest = i >> 5;          // rest = kp*32 + ic
        s_w[i] = Wx[(size_t)rest * OC + oc0 + oc];
    }
    __syncthreads();

    u64 p1[16], p2[16];
    #pragma unroll
    for (int q = 0; q < 16; q++) {
        u64 bv = pack2f(bias[oc0 + 2*q], bias[oc0 + 2*q + 1]);
        p1[q] = bv; p2[q] = bv;
    }

    #pragma unroll
    for (int kp = 0; kp < 9; kp++) {
        int ky = kp / 3, kx = kp - 3 * ky;
        int spb = (py + ky) * 34 + px + kx;
        const float* wk = s_w + kp * 1024;
        #pragma unroll 4
        for (int ic = 0; ic < CC; ic++) {
            u64 a1 = bcast2(s_in[ic * PS + spb]);
            u64 a2 = bcast2(s_in[ic * PS + spb + 272]);   // +8 rows
            const ulonglong2* w2 = (const ulonglong2*)(wk + ic * 32);
            #pragma unroll
            for (int j = 0; j < 8; j++) {
                ulonglong2 w = w2[j];
                fma2(p1[2*j],   a1, w.x); fma2(p1[2*j+1], a1, w.y);
                fma2(p2[2*j],   a2, w.x); fma2(p2[2*j+1], a2, w.y);
            }
        }
    }
    float* o1 = g_zx + (((size_t)bt * HH + y1) * WW + x) * OC + oc0;
    float* o2 = g_zx + (((size_t)bt * HH + y2) * WW + x) * OC + oc0;
    #pragma unroll
    for (int j = 0; j < 8; j++) {
        ((ulonglong2*)o1)[j] = make_ulonglong2(p1[2*j], p1[2*j+1]);
        ((ulonglong2*)o2)[j] = make_ulonglong2(p2[2*j], p2[2*j+1]);
    }
}

// ---------------- recurrent conv + fused LSTM gates -------------------------
// grid: (fb=8, tile=8, b=4).  Block handles f-channels [fb*8, fb*8+8) across
// all 4 gates (32 oc, gate-interleaved).  Epilogue computes c,h in registers.
// Reads h from hin, writes h to hout (double buffer; avoids grid-wide race).
__global__ __launch_bounds__(256, 2) void convh_kernel(const float* __restrict__ Wh,
                                                       const float* __restrict__ hin,
                                                       float* __restrict__ hout, int t) {
    extern __shared__ float sm[];
    float* s_in = sm;                 // 32 * 613 (one 32-channel chunk)
    float* s_w  = sm + 32 * PS;       // 9216

    int fb   = blockIdx.x;
    int tile = blockIdx.y;
    int b    = blockIdx.z;
    int tid  = threadIdx.x;
    int ty0 = (tile >> 1) * 16, tx0 = (tile & 1) * 32;
    int f0 = fb * 8;
    int px = tid & 31, py = tid >> 5;
    int y1 = ty0 + py, y2 = y1 + 8, x = tx0 + px;

    // acc layout: q = gate*4 + k  covers oc_local {gate*8+2k, gate*8+2k+1}
    u64 p1[16], p2[16];
    {
        const float* zb1 = g_zx + (((((size_t)b * TT) + t) * HH + y1) * WW + x) * OC;
        const float* zb2 = g_zx + (((((size_t)b * TT) + t) * HH + y2) * WW + x) * OC;
        #pragma unroll
        for (int g = 0; g < 4; g++) {
            const ulonglong2* zp1 = (const ulonglong2*)(zb1 + g * 64 + f0);
            const ulonglong2* zp2 = (const ulonglong2*)(zb2 + g * 64 + f0);
            ulonglong2 v0 = zp1[0], v1 = zp1[1];
            p1[g*4+0] = v0.x; p1[g*4+1] = v0.y; p1[g*4+2] = v1.x; p1[g*4+3] = v1.y;
            ulonglong2 w0 = zp2[0], w1 = zp2[1];
            p2[g*4+0] = w0.x; p2[g*4+1] = w0.y; p2[g*4+2] = w1.x; p2[g*4+3] = w1.y;
        }
    }

    const float* hb = hin + (size_t)b * HH * WW * FF;

    for (int ch0 = 0; ch0 < FF; ch0 += 32) {
        if (ch0) __syncthreads();
        for (int i = tid; i < 8 * HALO; i += 256) {
            int c4 = (i & 7) * 4, sp = i >> 3;
            int ry = sp / 34, rx = sp - ry * 34;
            int gy = ty0 - 1 + ry, gx = tx0 - 1 + rx;
            float4 v = make_float4(0.f, 0.f, 0.f, 0.f);
            if (gy >= 0 && gy < HH && gx >= 0 && gx < WW)
                v = *(const float4*)(hb + ((size_t)gy * WW + gx) * FF + ch0 + c4);
            s_in[(c4+0)*PS + sp] = v.x; s_in[(c4+1)*PS + sp] = v.y;
            s_in[(c4+2)*PS + sp] = v.z; s_in[(c4+3)*PS + sp] = v.w;
        }
        // weight chunk [kp][icl][gate*8+j]
        for (int i = tid; i < 9216; i += 256) {
            int ocl = i & 31, rest = i >> 5, kp = rest >> 5, icl = rest & 31;
            int gate = ocl >> 3, j = ocl & 7;
            s_w[i] = Wh[((size_t)kp * FF + ch0 + icl) * OC + gate * 64 + f0 + j];
        }
        __syncthreads();

        #pragma unroll
        for (int kp = 0; kp < 9; kp++) {
            int ky = kp / 3, kx = kp - 3 * ky;
            int spb = (py + ky) * 34 + px + kx;
            const float* wk = s_w + kp * 1024;
            #pragma unroll 4
            for (int icl = 0; icl < 32; icl++) {
                u64 a1 = bcast2(s_in[icl * PS + spb]);
                u64 a2 = bcast2(s_in[icl * PS + spb + 272]);
                const ulonglong2* w2 = (const ulonglong2*)(wk + icl * 32);
                #pragma unroll
                for (int j = 0; j < 8; j++) {
                    ulonglong2 w = w2[j];
                    fma2(p1[2*j],   a1, w.x); fma2(p1[2*j+1], a1, w.y);
                    fma2(p2[2*j],   a2, w.x); fma2(p2[2*j+1], a2, w.y);
                }
            }
        }
    }

    // ---- fused gate epilogue: both pixels ----
    #pragma unroll
    for (int pp = 0; pp < 2; pp++) {
        u64* P = pp ? p2 : p1;
        int y = pp ? y2 : y1;
        size_t pix = ((size_t)b * HH + y) * WW + x;
        float* cp = g_c  + pix * FF + f0;
        float* hp = hout + pix * FF + f0;
        #pragma unroll
        for (int k = 0; k < 4; k++) {   // 8 f-channels = 4 pairs
            float2 zi = unpack2(P[0*4 + k]);
            float2 zf = unpack2(P[1*4 + k]);
            float2 zc = unpack2(P[2*4 + k]);
            float2 zo = unpack2(P[3*4 + k]);
            float2 co = ((const float2*)cp)[k];
            float igx = __saturatef(0.2f*zi.x + 0.5f);
            float fgx = __saturatef(0.2f*zf.x + 0.5f);
            float ogx = __saturatef(0.2f*zo.x + 0.5f);
            float cx  = fgx * co.x + igx * tanhf(zc.x);
            float hx  = ogx * tanhf(cx);
            float igy = __saturatef(0.2f*zi.y + 0.5f);
            float fgy = __saturatef(0.2f*zf.y + 0.5f);
            float ogy = __saturatef(0.2f*zo.y + 0.5f);
            float cy  = fgy * co.y + igy * tanhf(zc.y);
            float hy  = ogy * tanhf(cy);
            ((float2*)cp)[k] = make_float2(cx, cy);
            ((float2*)hp)[k] = make_float2(hx, hy);
        }
    }
}

// ---------------- MaxPool (2x2) over h for one timestep ----------------------
__global__ void pool_kernel(const float* __restrict__ h, float* __restrict__ out, int t) {
    int i = blockIdx.x * blockDim.x + threadIdx.x;   // B*32*32*F = 262144
    if (i >= BB * 32 * 32 * FF) return;
    int f = i & 63;
    int r = i >> 6;
    int xo = r & 31; r >>= 5;
    int yo = r & 31;
    int b  = r >> 5;
    const float* hp = h + (((size_t)b * HH + yo * 2) * WW + xo * 2) * FF + f;
    float m = fmaxf(fmaxf(hp[0], hp[FF]),
                    fmaxf(hp[(size_t)WW * FF], hp[(size_t)WW * FF + FF]));
    out[(((((size_t)b * TT) + t) * 32 + yo) * 32 + xo) * FF + f] = m;
}

// ---------------- launch ----------------------------------------------------
extern "C" void kernel_launch(void* const* d_in, const int* in_sizes, int n_in,
                              void* d_out, int out_size) {
    const float* x     = (const float*)d_in[0];
    const float* gamma = (const float*)d_in[1];
    const float* beta  = (const float*)d_in[2];
    const float* Wx    = (const float*)d_in[3];
    const float* Wh    = (const float*)d_in[4];
    const float* bias  = (const float*)d_in[5];
    float* out = (float*)d_out;

    const int SMEM = (32 * PS + 9 * 32 * 32) * 4;   // 115328 B
    cudaFuncSetAttribute(convx_kernel, cudaFuncAttributeMaxDynamicSharedMemorySize, SMEM);
    cudaFuncSetAttribute(convh_kernel, cudaFuncAttributeMaxDynamicSharedMemorySize, SMEM);

    float *d_ha, *d_hb;
    cudaGetSymbolAddress((void**)&d_ha, g_ha);
    cudaGetSymbolAddress((void**)&d_hb, g_hb);

    // LayerNorm
    ln_kernel<<<(BB * TT * HH * WW) / 8, 256>>>(x, gamma, beta);

    // zero h(ping), c (every call: deterministic)
    zero_hc_kernel<<<(BB * HH * WW * FF + 255) / 256, 256>>>();

    // input conv over all timesteps at once
    convx_kernel<<<dim3(8, 8, BB * TT), 256, SMEM>>>(Wx, bias);

    // recurrent loop: h ping-pongs between g_ha and g_hb
    for (int t = 0; t < TT; t++) {
        const float* hin = (t & 1) ? d_hb : d_ha;
        float*       hout = (t & 1) ? d_ha : d_hb;
        convh_kernel<<<dim3(8, 8, BB), 256, SMEM>>>(Wh, hin, hout, t);
        pool_kernel<<<(BB * 32 * 32 * FF + 255) / 256, 256>>>(hout, out, t);
    }
}